// round 6
// baseline (speedup 1.0000x reference)
#include <cuda_runtime.h>

typedef unsigned long long u64;

constexpr int N      = 256;   // nA == nB
constexpr int R      = 8;     // batch rows per CTA
constexpr int NCTA   = 128;   // 1024 / 8
constexpr int NT     = 256;   // threads per CTA
constexpr int ITERS  = 51;    // 50 no-grad + 1 differentiable
constexpr int KROWS  = 192;   // K rows resident in smem
constexpr int KPAD   = 260;   // K row stride (floats): 1040B, 16B-aligned
constexpr int AF2S   = 16;    // AF2 row stride: [i][r][2] duplicated pairs
constexpr int BFP    = 260;   // BF row stride (floats)

constexpr int OFF_AF2     = KROWS * KPAD;          // 49920 floats
constexpr int OFF_BF      = OFF_AF2 + N * AF2S;    // +4096
constexpr int SMEM_FLOATS = OFF_BF + R * BFP;      // +2080
constexpr int SMEM_BYTES  = SMEM_FLOATS * 4;       // 224384 B <= 227KB

// ---- packed f32x2 helpers (sm_100+) ----
__device__ __forceinline__ u64 ffma2u(u64 a, u64 b, u64 c) {
    asm("fma.rn.f32x2 %0, %1, %2, %3;" : "=l"(c) : "l"(a), "l"(b), "l"(c));
    return c;
}
__device__ __forceinline__ void unpack2(u64 v, float& x, float& y) {
    asm("mov.b64 {%0, %1}, %2;" : "=f"(x), "=f"(y) : "l"(v));
}
__device__ __forceinline__ float hsum2(u64 v) {
    float x, y; unpack2(v, x, y); return x + y;
}
__device__ __forceinline__ ulonglong2 ldg128u(const float* p) {
    uint4 v = __ldg(reinterpret_cast<const uint4*>(p));
    ulonglong2 r;
    r.x = (u64)v.x | ((u64)v.y << 32);
    r.y = (u64)v.z | ((u64)v.w << 32);
    return r;
}

extern __shared__ float smem[];

__global__ __launch_bounds__(NT, 1)
void competitive_layer_kernel(const float* __restrict__ AT,
                              const float* __restrict__ BT,
                              const float* __restrict__ Kg,
                              float* __restrict__ C)
{
    float* Ks   = smem;                 // [KROWS][KPAD]
    float* AFs2 = smem + OFF_AF2;       // [N][R][2]  (each AF value duplicated)
    float* BFs  = smem + OFF_BF;        // [R][BFP]

    const int t    = threadIdx.x;
    const int row0 = blockIdx.x * R;
    const int rgrp = t & 3;             // r-pair group: r0 = 2*rgrp
    const int idx  = t >> 2;            // 0..63: GEMV1 i-base / GEMV2 j-quad
    const int r0   = 2 * rgrp;

    // ---- prologue: K rows [0,KROWS) -> smem ----
    {
        const float4* Kg4 = reinterpret_cast<const float4*>(Kg);
        for (int k = t; k < KROWS * (N / 4); k += NT) {
            int row = k >> 6, c4 = k & 63;
            float4 v = Kg4[row * 64 + c4];
            *reinterpret_cast<float4*>(&Ks[row * KPAD + c4 * 4]) = v;
        }
    }
    // ---- init BF = BT rows ----
    {
        const float4* BT4 = reinterpret_cast<const float4*>(BT + (size_t)row0 * N);
        for (int k = t; k < R * (N / 4); k += NT) {
            int r = k >> 6, c4 = k & 63;
            *reinterpret_cast<float4*>(&BFs[r * BFP + c4 * 4]) = BT4[r * 64 + c4];
        }
    }
    // ---- per-thread AT / BT values for owned outputs ----
    float at[4][2];                     // at[q][rr] for i = idx + 64q, r = r0 + rr
    #pragma unroll
    for (int q = 0; q < 4; q++)
        #pragma unroll
        for (int rr = 0; rr < 2; rr++)
            at[q][rr] = AT[(size_t)(row0 + r0 + rr) * N + idx + 64 * q];
    float4 btv[2];                      // BT[(row0+r0+rr)][4*idx .. +3]
    #pragma unroll
    for (int rr = 0; rr < 2; rr++)
        btv[rr] = *reinterpret_cast<const float4*>(BT + (size_t)(row0 + r0 + rr) * N + 4 * idx);

    // pointers (loop-invariant)
    const float* kp0 = Ks + idx * KPAD;           // GEMV1 rows q=0..2
    const float* kp1 = kp0 + 64 * KPAD;
    const float* kp2 = kp1 + 64 * KPAD;
    const float* gp1 = Kg + (size_t)(idx + 192) * N;   // GEMV1 row q=3 (L2)
    const float* bp0 = BFs + r0 * BFP;
    const float* bp1 = bp0 + BFP;
    const float* kcol = Ks + 4 * idx;             // GEMV2 smem rows
    const float* gcol = Kg + (size_t)KROWS * N + 4 * idx;  // GEMV2 tail rows (L2)
    const float* acol = AFs2 + 4 * rgrp;

    __syncthreads();

    #pragma unroll 1
    for (int it = 0; it < ITERS; it++) {
        // ======== GEMV1: AF[r][i] = at / (1 + sum_j K[i][j] * BF[r][j]) ========
        u64 acc[4][2];
        #pragma unroll
        for (int q = 0; q < 4; q++) { acc[q][0] = 0ull; acc[q][1] = 0ull; }

        #pragma unroll 4
        for (int j = 0; j < N; j += 4) {
            ulonglong2 k3 = ldg128u(gp1 + j);                                   // LDG (L2)
            ulonglong2 b0 = *reinterpret_cast<const ulonglong2*>(bp0 + j);      // 1 wf
            ulonglong2 b1 = *reinterpret_cast<const ulonglong2*>(bp1 + j);      // 1 wf
            ulonglong2 k0 = *reinterpret_cast<const ulonglong2*>(kp0 + j);      // 1 wf
            ulonglong2 k1 = *reinterpret_cast<const ulonglong2*>(kp1 + j);      // 1 wf
            ulonglong2 k2 = *reinterpret_cast<const ulonglong2*>(kp2 + j);      // 1 wf
            acc[0][0] = ffma2u(k0.x, b0.x, acc[0][0]); acc[0][0] = ffma2u(k0.y, b0.y, acc[0][0]);
            acc[0][1] = ffma2u(k0.x, b1.x, acc[0][1]); acc[0][1] = ffma2u(k0.y, b1.y, acc[0][1]);
            acc[1][0] = ffma2u(k1.x, b0.x, acc[1][0]); acc[1][0] = ffma2u(k1.y, b0.y, acc[1][0]);
            acc[1][1] = ffma2u(k1.x, b1.x, acc[1][1]); acc[1][1] = ffma2u(k1.y, b1.y, acc[1][1]);
            acc[2][0] = ffma2u(k2.x, b0.x, acc[2][0]); acc[2][0] = ffma2u(k2.y, b0.y, acc[2][0]);
            acc[2][1] = ffma2u(k2.x, b1.x, acc[2][1]); acc[2][1] = ffma2u(k2.y, b1.y, acc[2][1]);
            acc[3][0] = ffma2u(k3.x, b0.x, acc[3][0]); acc[3][0] = ffma2u(k3.y, b0.y, acc[3][0]);
            acc[3][1] = ffma2u(k3.x, b1.x, acc[3][1]); acc[3][1] = ffma2u(k3.y, b1.y, acc[3][1]);
        }
        // write AF duplicated: AFs2[i][r] = (v, v)
        #pragma unroll
        for (int q = 0; q < 4; q++) {
            int i = idx + 64 * q;
            #pragma unroll
            for (int rr = 0; rr < 2; rr++) {
                float v = __fdividef(at[q][rr], 1.0f + hsum2(acc[q][rr]));
                *reinterpret_cast<float2*>(&AFs2[i * AF2S + 4 * rgrp + 2 * rr]) =
                    make_float2(v, v);
            }
        }
        __syncthreads();

        // ======== GEMV2: BF[r][j] = bt / (1 + sum_i K[i][j] * AF[r][i]) ========
        u64 acc2[2][2];
        acc2[0][0] = acc2[0][1] = acc2[1][0] = acc2[1][1] = 0ull;

        #pragma unroll 4
        for (int i = 0; i < KROWS; i++) {
            ulonglong2 k2 = *reinterpret_cast<const ulonglong2*>(kcol + i * KPAD); // 1 wf
            ulonglong2 a2 = *reinterpret_cast<const ulonglong2*>(acol + i * AF2S); // 1 wf
            acc2[0][0] = ffma2u(k2.x, a2.x, acc2[0][0]);
            acc2[0][1] = ffma2u(k2.y, a2.x, acc2[0][1]);
            acc2[1][0] = ffma2u(k2.x, a2.y, acc2[1][0]);
            acc2[1][1] = ffma2u(k2.y, a2.y, acc2[1][1]);
        }
        #pragma unroll 8
        for (int i2 = 0; i2 < N - KROWS; i2++) {
            ulonglong2 k2 = ldg128u(gcol + (size_t)i2 * N);                        // LDG (L2)
            ulonglong2 a2 = *reinterpret_cast<const ulonglong2*>(acol + (KROWS + i2) * AF2S);
            acc2[0][0] = ffma2u(k2.x, a2.x, acc2[0][0]);
            acc2[0][1] = ffma2u(k2.y, a2.x, acc2[0][1]);
            acc2[1][0] = ffma2u(k2.x, a2.y, acc2[1][0]);
            acc2[1][1] = ffma2u(k2.y, a2.y, acc2[1][1]);
        }
        #pragma unroll
        for (int rr = 0; rr < 2; rr++) {
            float s0, s1, s2, s3;
            unpack2(acc2[rr][0], s0, s1);
            unpack2(acc2[rr][1], s2, s3);
            float4 o;
            o.x = __fdividef((&btv[rr].x)[0], 1.0f + s0);
            o.y = __fdividef((&btv[rr].x)[1], 1.0f + s1);
            o.z = __fdividef((&btv[rr].x)[2], 1.0f + s2);
            o.w = __fdividef((&btv[rr].x)[3], 1.0f + s3);
            *reinterpret_cast<float4*>(&BFs[(r0 + rr) * BFP + 4 * idx]) = o;
        }
        __syncthreads();
    }

    // ======== epilogue: C[row0+r][i][j] = K[i][j] * AF[r][i] * BF[r][j] ========
    #pragma unroll 1
    for (int r = 0; r < R; r++) {
        float* Crow = C + (size_t)(row0 + r) * N * N;
        for (int k = t; k < N * (N / 4); k += NT) {
            int i  = k >> 6;            // warp-uniform
            int j4 = k & 63;
            float4 k4;
            if (i < KROWS) k4 = *reinterpret_cast<const float4*>(&Ks[i * KPAD + j4 * 4]);
            else           k4 = __ldg(reinterpret_cast<const float4*>(&Kg[(size_t)i * N + j4 * 4]));
            float  a  = AFs2[i * AF2S + 2 * r];                                  // broadcast
            float4 b4 = *reinterpret_cast<const float4*>(&BFs[r * BFP + j4 * 4]);
            float4 o;
            o.x = k4.x * a * b4.x;
            o.y = k4.y * a * b4.y;
            o.z = k4.z * a * b4.z;
            o.w = k4.w * a * b4.w;
            *reinterpret_cast<float4*>(&Crow[i * N + j4 * 4]) = o;               // STG.128
        }
    }
}

extern "C" void kernel_launch(void* const* d_in, const int* in_sizes, int n_in,
                              void* d_out, int out_size)
{
    const float* AT = (const float*)d_in[0];   // [1024, 256]
    const float* BT = (const float*)d_in[1];   // [1024, 256]
    const float* Kg = (const float*)d_in[2];   // [256, 256]
    float*       C  = (float*)d_out;           // [1024, 256, 256]

    cudaFuncSetAttribute(competitive_layer_kernel,
                         cudaFuncAttributeMaxDynamicSharedMemorySize, SMEM_BYTES);
    competitive_layer_kernel<<<NCTA, NT, SMEM_BYTES>>>(AT, BT, Kg, C);
}